// round 12
// baseline (speedup 1.0000x reference)
#include <cuda_runtime.h>
#include <cuda_fp16.h>
#include <math.h>
#include <stdint.h>

#define D_MODEL   1024
#define N_EXPERTS 8
#define D_FF      4096
#define T_TOKENS  8192
#define TOTAL_SLOTS (T_TOKENS * 2)

#define BM_PAIR 256        // rows per cluster (128 per CTA)
#define BN 256             // two cg2 accumulators of N=128
#define BK 64              // fp16: 128B smem row = 64 halfs
#define NSTAGE 6
#define STAGE_B 32768      // A(16K) + B(16K: two 64-row halves) per stage

// smem layout (dynamic)
#define SM_TMEM  0
#define SM_FULL  16                        // full[6] @16..64  (leader-side, count 2)
#define SM_EMPTY (SM_FULL + NSTAGE * 8)    // empty[6] @64..112 (per-CTA, count 1)
#define SM_DONE  (SM_EMPTY + NSTAGE * 8)   // @112
#define SM_TILES 2048
#define SMEM_TOTAL (SM_TILES + NSTAGE * STAGE_B)   // 198656 B

// cg2 fp16 idesc: M=256 (16<<24), N=128 (16<<17), f32 accum (1<<4), a/b = F16
#define IDESC_CG2 ((16u << 24) | (16u << 17) | (1u << 4))

#if defined(__CUDA_ARCH__) && (defined(__CUDA_ARCH_FEAT_SM103_ALL) || defined(__CUDA_ARCH_FEAT_SM100_ALL) || defined(__CUDA_ARCH_FEAT_SM101_ALL))
#define USE_TCGEN05 1
#else
#define USE_TCGEN05 0
#endif

// ---------------- scratch (static __device__) ----------------
__device__ __half g_A1[(size_t)(TOTAL_SLOTS + BM_PAIR) * D_MODEL];
__device__ __half g_H[(size_t)(TOTAL_SLOTS + BM_PAIR) * D_FF];
__device__ float  g_Y[(size_t)TOTAL_SLOTS * D_MODEL];
__device__ __half g_W1t[(size_t)N_EXPERTS * D_FF * D_MODEL];      // [e][n][k]
__device__ __half g_W2t[(size_t)N_EXPERTS * D_MODEL * D_FF];      // [e][n][k]
__device__ int   g_slot_token[TOTAL_SLOTS];
__device__ int   g_tok2slot[T_TOKENS * 2];
__device__ float g_topk_w[T_TOKENS * 2];
__device__ int   g_topk_idx[T_TOKENS * 2];
__device__ int   g_cnt[N_EXPERTS];
__device__ int   g_off[N_EXPERTS + 1];
__device__ int   g_cursor[N_EXPERTS];

// ---------------- helpers ----------------
__device__ __forceinline__ float gelu_exact(float h) {
    return 0.5f * h * (1.0f + erff(h * 0.70710678118654752440f));
}
__device__ __forceinline__ uint32_t smem_u32(const void* p) {
    uint32_t a;
    asm("{ .reg .u64 t; cvta.to.shared.u64 t, %1; cvt.u32.u64 %0, t; }" : "=r"(a) : "l"(p));
    return a;
}

#if USE_TCGEN05
__device__ __forceinline__ uint32_t elect_one() {
    uint32_t pred;
    asm volatile("{\n\t.reg .pred p;\n\telect.sync _|p, 0xFFFFFFFF;\n\t"
                 "selp.b32 %0, 1, 0, p;\n\t}" : "=r"(pred));
    return pred;
}
static __device__ __forceinline__ uint64_t make_desc_sw128(uint32_t addr) {
    const uint64_t base = (uint64_t(2) << 61) | (uint64_t(1) << 46) |
                          (uint64_t(64) << 32) | (uint64_t(1) << 16);
    return base | ((uint64_t)(addr >> 4) & 0x3FFF);
}
// local wait (acquire.cta) — for tcgen05-commit empty/done barriers
__device__ __forceinline__ void mbar_wait(uint32_t mbar, uint32_t parity) {
    uint32_t done;
    asm volatile("{\n\t.reg .pred p;\n\t"
        "mbarrier.try_wait.parity.acquire.cta.shared::cta.b64 p, [%1], %2;\n\t"
        "selp.b32 %0, 1, 0, p;\n\t}"
        : "=r"(done) : "r"(mbar), "r"(parity) : "memory");
    while (!done) {
        asm volatile("{\n\t.reg .pred p;\n\t"
            "mbarrier.try_wait.parity.acquire.cta.shared::cta.b64 p, [%1], %2, 0x989680;\n\t"
            "selp.b32 %0, 1, 0, p;\n\t}"
            : "=r"(done) : "r"(mbar), "r"(parity) : "memory");
    }
}
// cluster-scope wait — for the cross-CTA full barrier (peer data visibility)
__device__ __forceinline__ void mbar_wait_cluster(uint32_t mbar, uint32_t parity) {
    uint32_t done;
    asm volatile("{\n\t.reg .pred p;\n\t"
        "mbarrier.try_wait.parity.acquire.cluster.shared::cta.b64 p, [%1], %2;\n\t"
        "selp.b32 %0, 1, 0, p;\n\t}"
        : "=r"(done) : "r"(mbar), "r"(parity) : "memory");
    while (!done) {
        asm volatile("{\n\t.reg .pred p;\n\t"
            "mbarrier.try_wait.parity.acquire.cluster.shared::cta.b64 p, [%1], %2, 0x989680;\n\t"
            "selp.b32 %0, 1, 0, p;\n\t}"
            : "=r"(done) : "r"(mbar), "r"(parity) : "memory");
    }
}
// arrive on leader (cluster rank 0) mbarrier at same smem offset
__device__ __forceinline__ void mbar_arrive_leader(uint32_t local_addr) {
    asm volatile("{\n\t.reg .b32 ra;\n\t"
                 "mapa.shared::cluster.u32 ra, %0, 0;\n\t"
                 "mbarrier.arrive.release.cluster.shared::cluster.b64 _, [ra];\n\t}"
                 :: "r"(local_addr) : "memory");
}
#define CP_ASYNC16(dst, src) \
    asm volatile("cp.async.cg.shared.global [%0], [%1], 16;" :: "r"(dst), "l"(src))
#define CP_COMMIT() asm volatile("cp.async.commit_group;" ::: "memory")
#define CP_WAITG(n) asm volatile("cp.async.wait_group %0;" :: "n"(n) : "memory")
#define CLUSTER_SYNC() do { \
    asm volatile("barrier.cluster.arrive.aligned;" ::: "memory"); \
    asm volatile("barrier.cluster.wait.aligned;" ::: "memory"); } while (0)

#define LDTM_X32(r, addr) \
    asm volatile( \
        "tcgen05.ld.sync.aligned.32x32b.x32.b32 " \
        "{%0, %1, %2, %3, %4, %5, %6, %7, " \
        " %8, %9, %10, %11, %12, %13, %14, %15, " \
        " %16, %17, %18, %19, %20, %21, %22, %23, " \
        " %24, %25, %26, %27, %28, %29, %30, %31}, [%32];" \
        : "=r"((r)[0]),  "=r"((r)[1]),  "=r"((r)[2]),  "=r"((r)[3]), \
          "=r"((r)[4]),  "=r"((r)[5]),  "=r"((r)[6]),  "=r"((r)[7]), \
          "=r"((r)[8]),  "=r"((r)[9]),  "=r"((r)[10]), "=r"((r)[11]), \
          "=r"((r)[12]), "=r"((r)[13]), "=r"((r)[14]), "=r"((r)[15]), \
          "=r"((r)[16]), "=r"((r)[17]), "=r"((r)[18]), "=r"((r)[19]), \
          "=r"((r)[20]), "=r"((r)[21]), "=r"((r)[22]), "=r"((r)[23]), \
          "=r"((r)[24]), "=r"((r)[25]), "=r"((r)[26]), "=r"((r)[27]), \
          "=r"((r)[28]), "=r"((r)[29]), "=r"((r)[30]), "=r"((r)[31]) \
        : "r"(addr))
#endif

// ---------------- routing kernels ----------------
__global__ void init_kernel() {
    int i = threadIdx.x;
    if (i < N_EXPERTS) g_cnt[i] = 0;
}

__global__ void gate_kernel(const float* __restrict__ x,
                            const float* __restrict__ Wg,
                            const float* __restrict__ bg,
                            float* __restrict__ gate_out)
{
    int warp = threadIdx.x >> 5;
    int lane = threadIdx.x & 31;
    int t = blockIdx.x * (blockDim.x >> 5) + warp;
    if (t >= T_TOKENS) return;

    float acc[N_EXPERTS];
#pragma unroll
    for (int e = 0; e < N_EXPERTS; e++) acc[e] = 0.0f;

    const float* xr = x + (size_t)t * D_MODEL;
    for (int d = lane; d < D_MODEL; d += 32) {
        float xv = xr[d];
        const float4 w0 = *(const float4*)(Wg + (size_t)d * N_EXPERTS);
        const float4 w1 = *(const float4*)(Wg + (size_t)d * N_EXPERTS + 4);
        acc[0] += xv * w0.x; acc[1] += xv * w0.y;
        acc[2] += xv * w0.z; acc[3] += xv * w0.w;
        acc[4] += xv * w1.x; acc[5] += xv * w1.y;
        acc[6] += xv * w1.z; acc[7] += xv * w1.w;
    }
#pragma unroll
    for (int e = 0; e < N_EXPERTS; e++) {
#pragma unroll
        for (int o = 16; o > 0; o >>= 1)
            acc[e] += __shfl_xor_sync(0xffffffffu, acc[e], o);
    }

    if (lane == 0) {
        float logit[N_EXPERTS];
        float mx = -1e30f;
#pragma unroll
        for (int e = 0; e < N_EXPERTS; e++) {
            logit[e] = acc[e] + bg[e];
            gate_out[(size_t)t * N_EXPERTS + e] = logit[e];
            mx = fmaxf(mx, logit[e]);
        }
        float p[N_EXPERTS];
        float sum = 0.0f;
#pragma unroll
        for (int e = 0; e < N_EXPERTS; e++) { p[e] = expf(logit[e] - mx); sum += p[e]; }
        float inv = 1.0f / sum;
#pragma unroll
        for (int e = 0; e < N_EXPERTS; e++) p[e] *= inv;

        int i0 = 0; float v0 = p[0];
#pragma unroll
        for (int e = 1; e < N_EXPERTS; e++) if (p[e] > v0) { v0 = p[e]; i0 = e; }
        int i1 = -1; float v1 = -1e30f;
#pragma unroll
        for (int e = 0; e < N_EXPERTS; e++) {
            if (e == i0) continue;
            if (p[e] > v1) { v1 = p[e]; i1 = e; }
        }
        g_topk_idx[t * 2 + 0] = i0; g_topk_w[t * 2 + 0] = v0;
        g_topk_idx[t * 2 + 1] = i1; g_topk_w[t * 2 + 1] = v1;
        atomicAdd(&g_cnt[i0], 1);
        atomicAdd(&g_cnt[i1], 1);
    }
}

__global__ void prefix_kernel() {
    if (threadIdx.x == 0) {
        int s = 0;
        for (int e = 0; e < N_EXPERTS; e++) {
            g_off[e] = s;
            g_cursor[e] = s;
            s += g_cnt[e];
        }
        g_off[N_EXPERTS] = s;
    }
}

__global__ void scatter_kernel() {
    int t = blockIdx.x * blockDim.x + threadIdx.x;
    if (t >= T_TOKENS) return;
#pragma unroll
    for (int k = 0; k < 2; k++) {
        int e = g_topk_idx[t * 2 + k];
        int pos = atomicAdd(&g_cursor[e], 1);
        g_slot_token[pos] = t;
        g_tok2slot[t * 2 + k] = pos;
    }
}

__global__ void gather_kernel(const float* __restrict__ x) {
    int idx = blockIdx.x * blockDim.x + threadIdx.x;
    int slot = idx >> 8;
    int c4 = idx & 255;
    int tok = g_slot_token[slot];
    float4 v = *(const float4*)(x + (size_t)tok * D_MODEL + c4 * 4);
    __half2 h0 = __floats2half2_rn(v.x, v.y);
    __half2 h1 = __floats2half2_rn(v.z, v.w);
    uint2 pk = make_uint2(*(uint32_t*)&h0, *(uint32_t*)&h1);
    *(uint2*)(g_A1 + (size_t)slot * D_MODEL + c4 * 4) = pk;
}

__global__ void transpose_kernel(const float* __restrict__ in, int R, int C, int which)
{
    __shared__ float tile[32][33];
    __half* out = which ? g_W2t : g_W1t;
    size_t base = (size_t)blockIdx.z * (size_t)R * C;
    int c0 = blockIdx.x * 32, r0 = blockIdx.y * 32;
    int tx = threadIdx.x & 31, ty = threadIdx.x >> 5;
#pragma unroll
    for (int i = 0; i < 32; i += 8)
        tile[ty + i][tx] = in[base + (size_t)(r0 + ty + i) * C + (c0 + tx)];
    __syncthreads();
#pragma unroll
    for (int q = 0; q < 2; q++) {
        int idx = threadIdx.x * 2 + q;
        int c = idx >> 4;
        int p = idx & 15;
        __half2 v = __floats2half2_rn(tile[2 * p][c], tile[2 * p + 1][c]);
        *(__half2*)(out + base + (size_t)(c0 + c) * R + (r0 + 2 * p)) = v;
    }
}

// ---------------- grouped GEMM: cg2 256x256 cluster tile, 6-stage cp.async ----------------
// MODE 0: H = fp16(gelu(A1 @ W1t^T + b1))   K=D_MODEL
// MODE 1: Y = H @ W2t^T + b2  (fp32)        K=D_FF
template<int KDIM, int MODE>
__global__ void __launch_bounds__(256, 1) __cluster_dims__(2, 1, 1)
moe_gemm(const float* __restrict__ bias)
{
    extern __shared__ char smem[];
    const int tid = threadIdx.x;
    const int wid = tid >> 5, lane = tid & 31;
    const uint32_t rank = (uint32_t)(blockIdx.x & 1);   // cluster rank along x

    const int e = blockIdx.z;
    const int mBase = g_off[e] + (blockIdx.x >> 1) * BM_PAIR;  // same for both ranks
    const int mEnd  = g_off[e + 1];
    if (mBase >= mEnd) return;                                  // pair exits together
    const int n0 = blockIdx.y * BN;

    const __half* Abase = (MODE == 0) ? g_A1 : g_H;
    const __half* Bt    = (MODE == 0) ? g_W1t : g_W2t;
    const int NB = (MODE == 0) ? D_FF : D_MODEL;
    const size_t eRowB = (size_t)e * NB;

#if USE_TCGEN05
    const uint32_t sb = smem_u32(smem);
    if (wid == 0) {
        asm volatile("tcgen05.alloc.cta_group::2.sync.aligned.shared::cta.b32 [%0], %1;"
                     :: "r"(sb + SM_TMEM), "r"(256u) : "memory");
        asm volatile("tcgen05.relinquish_alloc_permit.cta_group::2.sync.aligned;");
    }
    if (tid == 0) {
#pragma unroll
        for (int s = 0; s < NSTAGE; s++) {
            asm volatile("mbarrier.init.shared.b64 [%0], 2;"
                         :: "r"(sb + SM_FULL + s * 8) : "memory");   // 2 arrivals (both CTAs)
            asm volatile("mbarrier.init.shared.b64 [%0], 1;"
                         :: "r"(sb + SM_EMPTY + s * 8) : "memory");  // commit multicast
        }
        asm volatile("mbarrier.init.shared.b64 [%0], 1;" :: "r"(sb + SM_DONE) : "memory");
    }
    __syncthreads();
    CLUSTER_SYNC();   // barriers initialized in both CTAs before any cluster traffic
    const uint32_t tmem = *(const uint32_t*)(smem + SM_TMEM);

    // cp.async mapping: per CTA per stage 2048 16B units = 8/thread.
    //   units 0..1023  : A  (128 rows of this rank)
    //   units 1024..2047: B (two 64-row halves: acc-half nh, rows n0+nh*128+rank*64+r)
    uint32_t dstU[8];
    const char* srcU[8];
#pragma unroll
    for (int j = 0; j < 8; j++) {
        int u = tid + j * 256;           // 0..2047
        if (u < 1024) {
            int row = u >> 3, c16 = u & 7;
            uint32_t off = (uint32_t)(row * 128 + c16 * 16);
            dstU[j] = off ^ ((off >> 3) & 0x70);
            srcU[j] = (const char*)(Abase + (size_t)(mBase + rank * 128 + row) * KDIM) + c16 * 16;
        } else {
            int v = u - 1024;
            int nh = v >> 9;             // which 128-col accumulator
            int w = v & 511;
            int r64 = w >> 3, c16 = w & 7;
            uint32_t off = (uint32_t)(r64 * 128 + c16 * 16);
            uint32_t so = off ^ ((off >> 3) & 0x70);
            dstU[j] = 16384u + (uint32_t)nh * 8192u + so;
            int nrow = n0 + nh * 128 + (int)rank * 64 + r64;
            srcU[j] = (const char*)(Bt + (eRowB + nrow) * (size_t)KDIM) + c16 * 16;
        }
    }

    constexpr int NT = KDIM / BK;

#pragma unroll
    for (int p = 0; p < NSTAGE - 1; p++) {
        uint32_t sbase = sb + SM_TILES + p * STAGE_B;
        size_t koff = (size_t)p * 128;
#pragma unroll
        for (int j = 0; j < 8; j++) CP_ASYNC16(sbase + dstU[j], srcU[j] + koff);
        CP_COMMIT();
    }

    for (int k = 0; k < NT; k++) {
        const int s = k % NSTAGE;
        CP_WAITG(NSTAGE - 2);            // tile k's group locally complete
        __syncthreads();

        if (tid == 0) {
            asm volatile("fence.proxy.async.shared::cta;" ::: "memory");
            mbar_arrive_leader(sb + SM_FULL + s * 8);
        }
        if (rank == 0 && wid == 0 && elect_one()) {
            mbar_wait_cluster(sb + SM_FULL + s * 8, (uint32_t)(k / NSTAGE) & 1u);
            uint32_t st = sb + SM_TILES + s * STAGE_B;
            uint64_t ad = make_desc_sw128(st);
            uint64_t b0 = make_desc_sw128(st + 16384);
            uint64_t b1 = make_desc_sw128(st + 16384 + 8192);
#pragma unroll
            for (int sub = 0; sub < 4; sub++) {
                uint32_t en = (k > 0 || sub > 0) ? 1u : 0u;
#define MMA_CG2(dtm, adv, bdv) \
                asm volatile( \
                    "{\n\t.reg .pred p;\n\tsetp.ne.u32 p, %4, 0;\n\t" \
                    "tcgen05.mma.cta_group::2.kind::f16 [%0], %1, %2, %3, " \
                    "{%5, %5, %5, %5, %5, %5, %5, %5}, p;\n\t}" \
                    :: "r"(dtm), "l"(adv), "l"(bdv), "r"(IDESC_CG2), "r"(en), "r"(0u) \
                    : "memory")
                MMA_CG2(tmem +   0, ad + sub * 2, b0 + sub * 2);
                MMA_CG2(tmem + 128, ad + sub * 2, b1 + sub * 2);
#undef MMA_CG2
            }
            asm volatile(
                "tcgen05.commit.cta_group::2.mbarrier::arrive::one.shared::cluster.multicast::cluster.b64 [%0], %1;"
                :: "r"(sb + SM_EMPTY + s * 8), "h"((uint16_t)0x3) : "memory");
        }

        const int pend = k + NSTAGE - 1;
        if (pend < NT) {
            const int ps = pend % NSTAGE;
            if (pend >= NSTAGE) {
                uint32_t pr = ((uint32_t)(pend / NSTAGE) - 1u) & 1u;
                mbar_wait(sb + SM_EMPTY + ps * 8, pr);
            }
            uint32_t sbase = sb + SM_TILES + ps * STAGE_B;
            size_t koff = (size_t)pend * 128;
#pragma unroll
            for (int j = 0; j < 8; j++) CP_ASYNC16(sbase + dstU[j], srcU[j] + koff);
        }
        CP_COMMIT();
    }

    if (rank == 0 && wid == 0 && elect_one()) {
        asm volatile(
            "tcgen05.commit.cta_group::2.mbarrier::arrive::one.shared::cluster.multicast::cluster.b64 [%0], %1;"
            :: "r"(sb + SM_DONE), "h"((uint16_t)0x3) : "memory");
    }
    mbar_wait(sb + SM_DONE, 0);
    asm volatile("tcgen05.fence::after_thread_sync;" ::: "memory");

    // epilogue: each CTA reads its own 128 M-rows; warps 0-3 -> acc0, 4-7 -> acc1
    {
        const int acc = wid >> 2;
        const int row = (wid & 3) * 32 + lane;
        const int slot = mBase + (int)rank * 128 + row;
        const bool valid = slot < mEnd;
        const float* bb = bias + (size_t)e * NB + n0 + acc * 128;
        const uint32_t tm = tmem + acc * 128;
        __half* dstH = 0; float* dstY = 0;
        if (valid) {
            if (MODE == 0) dstH = g_H + (size_t)slot * D_FF + n0 + acc * 128;
            else           dstY = g_Y + (size_t)slot * D_MODEL + n0 + acc * 128;
        }
#pragma unroll
        for (int nb = 0; nb < 4; nb++) {
            uint32_t dr[32];
            LDTM_X32(dr, tm + nb * 32);
            asm volatile("tcgen05.wait::ld.sync.aligned;" ::: "memory");
            if (valid) {
#pragma unroll
                for (int q = 0; q < 8; q++) {
                    float v0 = __uint_as_float(dr[q * 4 + 0]) + bb[nb * 32 + q * 4 + 0];
                    float v1 = __uint_as_float(dr[q * 4 + 1]) + bb[nb * 32 + q * 4 + 1];
                    float v2 = __uint_as_float(dr[q * 4 + 2]) + bb[nb * 32 + q * 4 + 2];
                    float v3 = __uint_as_float(dr[q * 4 + 3]) + bb[nb * 32 + q * 4 + 3];
                    if (MODE == 0) {
                        __half2 h0 = __floats2half2_rn(gelu_exact(v0), gelu_exact(v1));
                        __half2 h1 = __floats2half2_rn(gelu_exact(v2), gelu_exact(v3));
                        uint2 pk = make_uint2(*(uint32_t*)&h0, *(uint32_t*)&h1);
                        *(uint2*)(dstH + nb * 32 + q * 4) = pk;
                    } else {
                        float4 o; o.x = v0; o.y = v1; o.z = v2; o.w = v3;
                        *(float4*)(dstY + nb * 32 + q * 4) = o;
                    }
                }
            }
        }
    }
    __syncthreads();
    if (wid == 0) {
        asm volatile("tcgen05.dealloc.cta_group::2.sync.aligned.b32 %0, %1;"
                     :: "r"(tmem), "r"(256u));
    }
    CLUSTER_SYNC();   // neither CTA exits while peer MMAs/SMEM reads could be in flight
#else
    // ---------- SIMT fallback (non-'a' pass only; runtime uses the 'a' cubin) ----------
    __syncthreads();
    float (*As)[132] = (float(*)[132])(smem + SM_TILES);
    float (*Bs)[132] = (float(*)[132])(smem + SM_TILES + 16 * 132 * 4);
    const int ty = tid >> 4, tx = tid & 15;
    const int lr = tid >> 1;
    const int lc = (tid & 1) * 8;

    const __half* arow = Abase + (size_t)(mBase + (int)rank * 128 + lr) * KDIM;
    for (int nh = 0; nh < 2; nh++) {
        const int nhh = n0 + nh * 128;
        const __half* brow = Bt + (eRowB + nhh + lr) * (size_t)KDIM + lc;
        float acc[8][8];
#pragma unroll
        for (int i = 0; i < 8; i++)
#pragma unroll
            for (int j = 0; j < 8; j++) acc[i][j] = 0.0f;

        for (int k0 = 0; k0 < KDIM; k0 += 16) {
#pragma unroll
            for (int q = 0; q < 8; q++) {
                As[lc + q][lr] = __half2float(arow[k0 + lc + q]);
                Bs[lc + q][lr] = __half2float(brow[k0 + q]);
            }
            __syncthreads();
#pragma unroll
            for (int kk = 0; kk < 16; kk++) {
                float a[8], bfr[8];
#pragma unroll
                for (int i = 0; i < 8; i++) a[i] = As[kk][ty * 8 + i];
#pragma unroll
                for (int j = 0; j < 8; j++) bfr[j] = Bs[kk][tx * 8 + j];
#pragma unroll
                for (int i = 0; i < 8; i++)
#pragma unroll
                    for (int j = 0; j < 8; j++) acc[i][j] += a[i] * bfr[j];
            }
            __syncthreads();
        }
        const float* bb = bias + (size_t)e * NB + nhh;
#pragma unroll
        for (int i = 0; i < 8; i++) {
            int slot = mBase + (int)rank * 128 + ty * 8 + i;
            if (slot >= mEnd) continue;
#pragma unroll
            for (int j = 0; j < 8; j++) {
                float v = acc[i][j] + bb[tx * 8 + j];
                if (MODE == 0)
                    g_H[(size_t)slot * D_FF + nhh + tx * 8 + j] = __float2half_rn(gelu_exact(v));
                else
                    g_Y[(size_t)slot * D_MODEL + nhh + tx * 8 + j] = v;
            }
        }
        __syncthreads();
    }
#endif
}

// ---------------- combine ----------------
__global__ void combine_kernel(float* __restrict__ out) {
    int idx = blockIdx.x * blockDim.x + threadIdx.x;
    int t  = idx >> 8;
    int d4 = idx & 255;
    int s0 = g_tok2slot[t * 2 + 0], s1 = g_tok2slot[t * 2 + 1];
    float w0 = g_topk_w[t * 2 + 0], w1 = g_topk_w[t * 2 + 1];
    float4 a = *(const float4*)(g_Y + (size_t)s0 * D_MODEL + d4 * 4);
    float4 b = *(const float4*)(g_Y + (size_t)s1 * D_MODEL + d4 * 4);
    float4 o;
    o.x = w0 * a.x + w1 * b.x;
    o.y = w0 * a.y + w1 * b.y;
    o.z = w0 * a.z + w1 * b.z;
    o.w = w0 * a.w + w1 * b.w;
    *(float4*)(out + (size_t)t * D_MODEL + d4 * 4) = o;
}

// ---------------- host launch ----------------
extern "C" void kernel_launch(void* const* d_in, const int* in_sizes, int n_in,
                              void* d_out, int out_size)
{
    const float* x  = (const float*)d_in[0];
    const float* Wg = (const float*)d_in[1];
    const float* bg = (const float*)d_in[2];
    const float* W1 = (const float*)d_in[3];
    const float* b1 = (const float*)d_in[4];
    const float* W2 = (const float*)d_in[5];
    const float* b2 = (const float*)d_in[6];
    float* out = (float*)d_out;

    cudaFuncSetAttribute(moe_gemm<D_MODEL, 0>,
                         cudaFuncAttributeMaxDynamicSharedMemorySize, SMEM_TOTAL);
    cudaFuncSetAttribute(moe_gemm<D_FF, 1>,
                         cudaFuncAttributeMaxDynamicSharedMemorySize, SMEM_TOTAL);

    transpose_kernel<<<dim3(D_FF / 32, D_MODEL / 32, N_EXPERTS), 256>>>(W1, D_MODEL, D_FF, 0);
    transpose_kernel<<<dim3(D_MODEL / 32, D_FF / 32, N_EXPERTS), 256>>>(W2, D_FF, D_MODEL, 1);

    init_kernel<<<1, 32>>>();
    gate_kernel<<<T_TOKENS / 8, 256>>>(x, Wg, bg, out + (size_t)T_TOKENS * D_MODEL);
    prefix_kernel<<<1, 32>>>();
    scatter_kernel<<<T_TOKENS / 256, 256>>>();
    gather_kernel<<<(TOTAL_SLOTS * 256) / 256, 256>>>(x);

    // grid.x = CTAs of 128 rows; clusters of 2 along x cover 256-row pairs
    dim3 g1(TOTAL_SLOTS / 128, D_FF / BN, N_EXPERTS);
    moe_gemm<D_MODEL, 0><<<g1, 256, SMEM_TOTAL>>>(b1);

    dim3 g2(TOTAL_SLOTS / 128, D_MODEL / BN, N_EXPERTS);
    moe_gemm<D_FF, 1><<<g2, 256, SMEM_TOTAL>>>(b2);

    combine_kernel<<<(T_TOKENS * 256) / 256, 256>>>(out);
}

// round 14
// speedup vs baseline: 1.6111x; 1.6111x over previous
#include <cuda_runtime.h>
#include <cuda_fp16.h>
#include <math.h>
#include <stdint.h>

#define D_MODEL   1024
#define N_EXPERTS 8
#define D_FF      4096
#define T_TOKENS  8192
#define TOTAL_SLOTS (T_TOKENS * 2)

#define BM 256            // two 128-row A tiles
#define BN 256            // two 128-col B tiles
#define BK 64             // fp16: 128B smem row = 64 halfs
#define NSTAGE 3
#define TILE16K 16384
#define STAGE_B (4 * TILE16K)        // A0 + A1 + B0 + B1 per stage

// smem layout (dynamic)
#define SM_TMEM  0
#define SM_MBAR  16                  // empty[NSTAGE] @16.., done after
#define SM_DONE  (SM_MBAR + NSTAGE * 8)
#define SM_TILES 2048
#define SMEM_TOTAL (SM_TILES + NSTAGE * STAGE_B)   // 198656 B

// fp16 idesc: M=128 (8<<24), N=128 (16<<17), f32 accum (1<<4), a/b = F16 (0)
#define IDESC_F16 ((8u << 24) | (16u << 17) | (1u << 4))

#if defined(__CUDA_ARCH__) && (defined(__CUDA_ARCH_FEAT_SM103_ALL) || defined(__CUDA_ARCH_FEAT_SM100_ALL) || defined(__CUDA_ARCH_FEAT_SM101_ALL))
#define USE_TCGEN05 1
#else
#define USE_TCGEN05 0
#endif

// ---------------- scratch (static __device__) ----------------
__device__ __half g_A1[(size_t)(TOTAL_SLOTS + BM) * D_MODEL];     // gathered fp16 x
__device__ __half g_H[(size_t)(TOTAL_SLOTS + BM) * D_FF];         // fp16 activations
__device__ __half g_W1t[(size_t)N_EXPERTS * D_FF * D_MODEL];      // [e][n][k] fp16
__device__ __half g_W2t[(size_t)N_EXPERTS * D_MODEL * D_FF];      // [e][n][k] fp16
__device__ int   g_slot_token[TOTAL_SLOTS];
__device__ float g_slot_w[TOTAL_SLOTS];
__device__ float g_topk_w[T_TOKENS * 2];
__device__ int   g_topk_idx[T_TOKENS * 2];
__device__ int   g_cnt[N_EXPERTS];
__device__ int   g_off[N_EXPERTS + 1];
__device__ int   g_cursor[N_EXPERTS];

// ---------------- helpers ----------------
__device__ __forceinline__ float gelu_exact(float h) {
    return 0.5f * h * (1.0f + erff(h * 0.70710678118654752440f));
}
__device__ __forceinline__ uint32_t smem_u32(const void* p) {
    uint32_t a;
    asm("{ .reg .u64 t; cvta.to.shared.u64 t, %1; cvt.u32.u64 %0, t; }" : "=r"(a) : "l"(p));
    return a;
}

#if USE_TCGEN05
__device__ __forceinline__ uint32_t elect_one() {
    uint32_t pred;
    asm volatile("{\n\t.reg .pred p;\n\telect.sync _|p, 0xFFFFFFFF;\n\t"
                 "selp.b32 %0, 1, 0, p;\n\t}" : "=r"(pred));
    return pred;
}
static __device__ __forceinline__ uint64_t make_desc_sw128(uint32_t addr) {
    const uint64_t base = (uint64_t(2) << 61) | (uint64_t(1) << 46) |
                          (uint64_t(64) << 32) | (uint64_t(1) << 16);
    return base | ((uint64_t)(addr >> 4) & 0x3FFF);
}
__device__ __forceinline__ void mbar_wait(uint32_t mbar, uint32_t parity) {
    uint32_t done;
    asm volatile("{\n\t.reg .pred p;\n\t"
        "mbarrier.try_wait.parity.acquire.cta.shared::cta.b64 p, [%1], %2;\n\t"
        "selp.b32 %0, 1, 0, p;\n\t}"
        : "=r"(done) : "r"(mbar), "r"(parity) : "memory");
    while (!done) {
        asm volatile("{\n\t.reg .pred p;\n\t"
            "mbarrier.try_wait.parity.acquire.cta.shared::cta.b64 p, [%1], %2, 0x989680;\n\t"
            "selp.b32 %0, 1, 0, p;\n\t}"
            : "=r"(done) : "r"(mbar), "r"(parity) : "memory");
    }
}
#define CP_ASYNC16(dst, src) \
    asm volatile("cp.async.cg.shared.global [%0], [%1], 16;" :: "r"(dst), "l"(src))
#define CP_COMMIT() asm volatile("cp.async.commit_group;" ::: "memory")
#define CP_WAIT1()  asm volatile("cp.async.wait_group 1;" ::: "memory")

#define LDTM_X32(r, addr) \
    asm volatile( \
        "tcgen05.ld.sync.aligned.32x32b.x32.b32 " \
        "{%0, %1, %2, %3, %4, %5, %6, %7, " \
        " %8, %9, %10, %11, %12, %13, %14, %15, " \
        " %16, %17, %18, %19, %20, %21, %22, %23, " \
        " %24, %25, %26, %27, %28, %29, %30, %31}, [%32];" \
        : "=r"((r)[0]),  "=r"((r)[1]),  "=r"((r)[2]),  "=r"((r)[3]), \
          "=r"((r)[4]),  "=r"((r)[5]),  "=r"((r)[6]),  "=r"((r)[7]), \
          "=r"((r)[8]),  "=r"((r)[9]),  "=r"((r)[10]), "=r"((r)[11]), \
          "=r"((r)[12]), "=r"((r)[13]), "=r"((r)[14]), "=r"((r)[15]), \
          "=r"((r)[16]), "=r"((r)[17]), "=r"((r)[18]), "=r"((r)[19]), \
          "=r"((r)[20]), "=r"((r)[21]), "=r"((r)[22]), "=r"((r)[23]), \
          "=r"((r)[24]), "=r"((r)[25]), "=r"((r)[26]), "=r"((r)[27]), \
          "=r"((r)[28]), "=r"((r)[29]), "=r"((r)[30]), "=r"((r)[31]) \
        : "r"(addr))
#endif

// ---------------- routing kernels ----------------
__global__ void init_kernel() {
    int i = threadIdx.x;
    if (i < N_EXPERTS) g_cnt[i] = 0;
}

// gate v2: Wg staged in smem e-major; 64 tokens per block (8 per warp)
__global__ __launch_bounds__(256) void gate_kernel(const float* __restrict__ x,
                                                   const float* __restrict__ Wg,
                                                   const float* __restrict__ bg,
                                                   float* __restrict__ gate_out)
{
    __shared__ float sWg[N_EXPERTS][1032];   // [e][d], padded
    __shared__ float sbg[N_EXPERTS];
    const int tid = threadIdx.x;
#pragma unroll
    for (int i = 0; i < 32; i++) {
        int idx = tid + i * 256;             // 0..8191 over [d][e]
        sWg[idx & 7][idx >> 3] = Wg[idx];
    }
    if (tid < N_EXPERTS) sbg[tid] = bg[tid];
    __syncthreads();

    const int warp = tid >> 5, lane = tid & 31;
#pragma unroll 1
    for (int j = 0; j < 8; j++) {
        const int t = blockIdx.x * 64 + warp * 8 + j;
        const float4* xr = (const float4*)(x + (size_t)t * D_MODEL);
        float acc[N_EXPERTS];
#pragma unroll
        for (int e = 0; e < N_EXPERTS; e++) acc[e] = 0.0f;
#pragma unroll
        for (int i = 0; i < 8; i++) {
            const int d4 = lane + i * 32;
            float4 xv = xr[d4];
#pragma unroll
            for (int e = 0; e < N_EXPERTS; e++) {
                float4 wv = *(const float4*)&sWg[e][d4 * 4];
                acc[e] += xv.x * wv.x + xv.y * wv.y + xv.z * wv.z + xv.w * wv.w;
            }
        }
#pragma unroll
        for (int e = 0; e < N_EXPERTS; e++) {
#pragma unroll
            for (int o = 16; o > 0; o >>= 1)
                acc[e] += __shfl_xor_sync(0xffffffffu, acc[e], o);
        }
        if (lane == 0) {
            float logit[N_EXPERTS];
            float mx = -1e30f;
#pragma unroll
            for (int e = 0; e < N_EXPERTS; e++) {
                logit[e] = acc[e] + sbg[e];
                gate_out[(size_t)t * N_EXPERTS + e] = logit[e];
                mx = fmaxf(mx, logit[e]);
            }
            float p[N_EXPERTS];
            float sum = 0.0f;
#pragma unroll
            for (int e = 0; e < N_EXPERTS; e++) { p[e] = expf(logit[e] - mx); sum += p[e]; }
            float inv = 1.0f / sum;
#pragma unroll
            for (int e = 0; e < N_EXPERTS; e++) p[e] *= inv;

            int i0 = 0; float v0 = p[0];
#pragma unroll
            for (int e = 1; e < N_EXPERTS; e++) if (p[e] > v0) { v0 = p[e]; i0 = e; }
            int i1 = -1; float v1 = -1e30f;
#pragma unroll
            for (int e = 0; e < N_EXPERTS; e++) {
                if (e == i0) continue;
                if (p[e] > v1) { v1 = p[e]; i1 = e; }
            }
            g_topk_idx[t * 2 + 0] = i0; g_topk_w[t * 2 + 0] = v0;
            g_topk_idx[t * 2 + 1] = i1; g_topk_w[t * 2 + 1] = v1;
            atomicAdd(&g_cnt[i0], 1);
            atomicAdd(&g_cnt[i1], 1);
        }
    }
}

__global__ void prefix_kernel() {
    if (threadIdx.x == 0) {
        int s = 0;
        for (int e = 0; e < N_EXPERTS; e++) {
            g_off[e] = s;
            g_cursor[e] = s;
            s += g_cnt[e];
        }
        g_off[N_EXPERTS] = s;
    }
}

__global__ void scatter_kernel() {
    int t = blockIdx.x * blockDim.x + threadIdx.x;
    if (t >= T_TOKENS) return;
#pragma unroll
    for (int k = 0; k < 2; k++) {
        int e = g_topk_idx[t * 2 + k];
        int pos = atomicAdd(&g_cursor[e], 1);
        g_slot_token[pos] = t;
        g_slot_w[pos] = g_topk_w[t * 2 + k];
    }
}

// gather + fp16-convert x rows into slot order
__global__ void gather_kernel(const float* __restrict__ x) {
    int idx = blockIdx.x * blockDim.x + threadIdx.x;
    int slot = idx >> 8;
    int c4 = idx & 255;
    int tok = g_slot_token[slot];
    float4 v = *(const float4*)(x + (size_t)tok * D_MODEL + c4 * 4);
    __half2 h0 = __floats2half2_rn(v.x, v.y);
    __half2 h1 = __floats2half2_rn(v.z, v.w);
    uint2 pk = make_uint2(*(uint32_t*)&h0, *(uint32_t*)&h1);
    *(uint2*)(g_A1 + (size_t)slot * D_MODEL + c4 * 4) = pk;
}

// transpose v2 + fp16 convert: in [z][R][C] fp32 -> out [z][C][R] fp16
// 64(rows) x 32(cols) tile; each thread writes one 16B uint4 of fp16 (coalesced)
__global__ __launch_bounds__(256) void transpose_kernel(const float* __restrict__ in,
                                                        int R, int C, int which)
{
    __shared__ float tile[64][33];
    __half* out = which ? g_W2t : g_W1t;
    size_t base = (size_t)blockIdx.z * (size_t)R * C;
    int c0 = blockIdx.x * 32, r0 = blockIdx.y * 64;
    int tid = threadIdx.x;

    // load: 64 rows x 32 cols; threads 0..3 cover row 0 (128B contiguous)
    {
        int r = tid >> 2;
        int cg = (tid & 3) * 8;
        const float* src = in + base + (size_t)(r0 + r) * C + c0 + cg;
        float4 v0 = *(const float4*)(src);
        float4 v1 = *(const float4*)(src + 4);
        tile[r][cg + 0] = v0.x; tile[r][cg + 1] = v0.y;
        tile[r][cg + 2] = v0.z; tile[r][cg + 3] = v0.w;
        tile[r][cg + 4] = v1.x; tile[r][cg + 5] = v1.y;
        tile[r][cg + 6] = v1.z; tile[r][cg + 7] = v1.w;
    }
    __syncthreads();

    // write: 32 out-rows (each col c), 64 fp16 = 128B per row = 8 threads x 16B
    {
        int c = tid >> 3;
        int rg = (tid & 7) * 8;
        __half2 h0 = __floats2half2_rn(tile[rg + 0][c], tile[rg + 1][c]);
        __half2 h1 = __floats2half2_rn(tile[rg + 2][c], tile[rg + 3][c]);
        __half2 h2 = __floats2half2_rn(tile[rg + 4][c], tile[rg + 5][c]);
        __half2 h3 = __floats2half2_rn(tile[rg + 6][c], tile[rg + 7][c]);
        uint4 pk;
        pk.x = *(uint32_t*)&h0; pk.y = *(uint32_t*)&h1;
        pk.z = *(uint32_t*)&h2; pk.w = *(uint32_t*)&h3;
        *(uint4*)(out + base + (size_t)(c0 + c) * R + (r0 + rg)) = pk;
    }
}

// ---------------- grouped GEMM (tcgen05 fp16, 256x256 tile, 3-stage ring) ----------------
// MODE 0: H[slot] = fp16(gelu(A1[slot] @ W1t^T + b1))        K=D_MODEL, N=D_FF
// MODE 1: out[tok] += w * (H[slot] @ W2t^T + b2)  (atomic)   K=D_FF,    N=D_MODEL
template<int KDIM, int MODE>
__global__ void __launch_bounds__(256, 1) moe_gemm(const float* __restrict__ bias,
                                                   float* __restrict__ out)
{
    extern __shared__ char smem[];
    const int tid = threadIdx.x;
    const int wid = tid >> 5, lane = tid & 31;

    const int e = blockIdx.z;
    const int mBase = g_off[e] + blockIdx.x * BM;
    const int mEnd  = g_off[e + 1];
    if (mBase >= mEnd) return;
    const int n0 = blockIdx.y * BN;

    const __half* Abase = (MODE == 0) ? g_A1 : g_H;
    const __half* Bt    = (MODE == 0) ? g_W1t : g_W2t;
    const int NB = (MODE == 0) ? D_FF : D_MODEL;
    const size_t eRowB = (size_t)e * NB;

#if USE_TCGEN05
    const uint32_t sb = smem_u32(smem);
    if (wid == 0) {
        asm volatile("tcgen05.alloc.cta_group::1.sync.aligned.shared::cta.b32 [%0], %1;"
                     :: "r"(sb + SM_TMEM), "r"(512u) : "memory");
        asm volatile("tcgen05.relinquish_alloc_permit.cta_group::1.sync.aligned;");
    }
    if (tid == 0) {
#pragma unroll
        for (int s = 0; s < NSTAGE; s++)
            asm volatile("mbarrier.init.shared.b64 [%0], 1;"
                         :: "r"(sb + SM_MBAR + s * 8) : "memory");
        asm volatile("mbarrier.init.shared.b64 [%0], 1;" :: "r"(sb + SM_DONE) : "memory");
    }
    __syncthreads();
    const uint32_t tmem = *(const uint32_t*)(smem + SM_TMEM);

    uint32_t dstU[16];
    const char* srcU[16];
#pragma unroll
    for (int j = 0; j < 16; j++) {
        int u = tid + j * 256;
        int tile = u >> 10;              // 0=A0,1=A1,2=B0,3=B1
        int v = u & 1023;
        int row = v >> 3, c16 = v & 7;
        uint32_t off = (uint32_t)(row * 128 + c16 * 16);
        uint32_t so = off ^ ((off >> 3) & 0x70);
        dstU[j] = (uint32_t)tile * TILE16K + so;
        const __half* src;
        if (tile < 2)
            src = Abase + (size_t)(mBase + tile * 128 + row) * KDIM;
        else
            src = Bt + (eRowB + n0 + (tile - 2) * 128 + row) * (size_t)KDIM;
        srcU[j] = (const char*)src + c16 * 16;
    }

    constexpr int NT = KDIM / BK;

#pragma unroll
    for (int p = 0; p < NSTAGE - 1; p++) {
        uint32_t sbase = sb + SM_TILES + p * STAGE_B;
        size_t koff = (size_t)p * 128;
#pragma unroll
        for (int j = 0; j < 16; j++) CP_ASYNC16(sbase + dstU[j], srcU[j] + koff);
        CP_COMMIT();
    }

    for (int k = 0; k < NT; k++) {
        const int s = k % NSTAGE;
        CP_WAIT1();
        __syncthreads();

        if (wid == 0 && elect_one()) {
            asm volatile("fence.proxy.async.shared::cta;" ::: "memory");
            uint32_t st = sb + SM_TILES + s * STAGE_B;
            uint64_t a0 = make_desc_sw128(st);
            uint64_t a1 = make_desc_sw128(st + TILE16K);
            uint64_t b0 = make_desc_sw128(st + 2 * TILE16K);
            uint64_t b1 = make_desc_sw128(st + 3 * TILE16K);
#pragma unroll
            for (int sub = 0; sub < 4; sub++) {
                uint32_t en = (k > 0 || sub > 0) ? 1u : 0u;
#define MMA_F16(dtm, ad, bd) \
                asm volatile( \
                    "{\n\t.reg .pred p;\n\tsetp.ne.u32 p, %4, 0;\n\t" \
                    "tcgen05.mma.cta_group::1.kind::f16 [%0], %1, %2, %3, " \
                    "{%5, %5, %5, %5}, p;\n\t}" \
                    :: "r"(dtm), "l"(ad), "l"(bd), "r"(IDESC_F16), "r"(en), "r"(0u) \
                    : "memory")
                MMA_F16(tmem +   0, a0 + sub * 2, b0 + sub * 2);
                MMA_F16(tmem + 128, a0 + sub * 2, b1 + sub * 2);
                MMA_F16(tmem + 256, a1 + sub * 2, b0 + sub * 2);
                MMA_F16(tmem + 384, a1 + sub * 2, b1 + sub * 2);
#undef MMA_F16
            }
            asm volatile(
                "tcgen05.commit.cta_group::1.mbarrier::arrive::one.shared::cluster.b64 [%0];"
                :: "r"(sb + SM_MBAR + s * 8) : "memory");
        }

        const int pend = k + NSTAGE - 1;
        if (pend < NT) {
            const int ps = pend % NSTAGE;
            if (pend >= NSTAGE) {
                uint32_t pr = ((uint32_t)(pend / NSTAGE) - 1u) & 1u;
                mbar_wait(sb + SM_MBAR + ps * 8, pr);
            }
            uint32_t sbase = sb + SM_TILES + ps * STAGE_B;
            size_t koff = (size_t)pend * 128;
#pragma unroll
            for (int j = 0; j < 16; j++) CP_ASYNC16(sbase + dstU[j], srcU[j] + koff);
        }
        CP_COMMIT();
    }

    if (wid == 0 && elect_one()) {
        asm volatile(
            "tcgen05.commit.cta_group::1.mbarrier::arrive::one.shared::cluster.b64 [%0];"
            :: "r"(sb + SM_DONE) : "memory");
    }
    mbar_wait(sb + SM_DONE, 0);
    asm volatile("tcgen05.fence::after_thread_sync;" ::: "memory");

    // epilogue: warps 0-3 -> m-half 0 (acc @0,@128), warps 4-7 -> m-half 1 (@256,@384)
    {
        const int mh = wid >> 2;
        const int row = (wid & 3) * 32 + lane;
        const int slot = mBase + mh * 128 + row;
        const bool valid = slot < mEnd;
        int tok = 0; float w = 0.0f;
        if (MODE == 1 && valid) { tok = g_slot_token[slot]; w = g_slot_w[slot]; }
#pragma unroll
        for (int nh = 0; nh < 2; nh++) {
            const float* bb = bias + (size_t)e * NB + n0 + nh * 128;
            const uint32_t tm = tmem + mh * 256 + nh * 128;
            __half* dstH = 0; float* dstO = 0;
            if (valid) {
                if (MODE == 0) dstH = g_H + (size_t)slot * D_FF + n0 + nh * 128;
                else           dstO = out + (size_t)tok * D_MODEL + n0 + nh * 128;
            }
#pragma unroll
            for (int nb = 0; nb < 4; nb++) {
                uint32_t dr[32];
                LDTM_X32(dr, tm + nb * 32);
                asm volatile("tcgen05.wait::ld.sync.aligned;" ::: "memory");
                if (valid) {
#pragma unroll
                    for (int q = 0; q < 8; q++) {
                        float v0 = __uint_as_float(dr[q * 4 + 0]) + bb[nb * 32 + q * 4 + 0];
                        float v1 = __uint_as_float(dr[q * 4 + 1]) + bb[nb * 32 + q * 4 + 1];
                        float v2 = __uint_as_float(dr[q * 4 + 2]) + bb[nb * 32 + q * 4 + 2];
                        float v3 = __uint_as_float(dr[q * 4 + 3]) + bb[nb * 32 + q * 4 + 3];
                        if (MODE == 0) {
                            __half2 h0 = __floats2half2_rn(gelu_exact(v0), gelu_exact(v1));
                            __half2 h1 = __floats2half2_rn(gelu_exact(v2), gelu_exact(v3));
                            uint2 pk = make_uint2(*(uint32_t*)&h0, *(uint32_t*)&h1);
                            *(uint2*)(dstH + nb * 32 + q * 4) = pk;
                        } else {
                            atomicAdd(dstO + nb * 32 + q * 4 + 0, w * v0);
                            atomicAdd(dstO + nb * 32 + q * 4 + 1, w * v1);
                            atomicAdd(dstO + nb * 32 + q * 4 + 2, w * v2);
                            atomicAdd(dstO + nb * 32 + q * 4 + 3, w * v3);
                        }
                    }
                }
            }
        }
    }
    __syncthreads();
    if (wid == 0) {
        asm volatile("tcgen05.dealloc.cta_group::1.sync.aligned.b32 %0, %1;"
                     :: "r"(tmem), "r"(512u));
    }
#else
    // ---------- SIMT fallback (non-'a' pass only; runtime uses the 'a' cubin) ----------
    __syncthreads();
    float (*As)[132] = (float(*)[132])(smem + SM_TILES);
    float (*Bs)[132] = (float(*)[132])(smem + SM_TILES + 16 * 132 * 4);
    const int ty = tid >> 4, tx = tid & 15;
    const int lr = tid >> 1;
    const int lc = (tid & 1) * 8;

    for (int mh = 0; mh < 2; mh++) {
        const __half* arow = Abase + (size_t)(mBase + mh * 128 + lr) * KDIM;
        for (int nh = 0; nh < 2; nh++) {
            const int nhh = n0 + nh * 128;
            const __half* brow = Bt + (eRowB + nhh + lr) * (size_t)KDIM + lc;
            float acc[8][8];
#pragma unroll
            for (int i = 0; i < 8; i++)
#pragma unroll
                for (int j = 0; j < 8; j++) acc[i][j] = 0.0f;

            for (int k0 = 0; k0 < KDIM; k0 += 16) {
#pragma unroll
                for (int q = 0; q < 8; q++) {
                    As[lc + q][lr] = __half2float(arow[k0 + lc + q]);
                    Bs[lc + q][lr] = __half2float(brow[k0 + q]);
                }
                __syncthreads();
#pragma unroll
                for (int kk = 0; kk < 16; kk++) {
                    float a[8], bfr[8];
#pragma unroll
                    for (int i = 0; i < 8; i++) a[i] = As[kk][ty * 8 + i];
#pragma unroll
                    for (int j = 0; j < 8; j++) bfr[j] = Bs[kk][tx * 8 + j];
#pragma unroll
                    for (int i = 0; i < 8; i++)
#pragma unroll
                        for (int j = 0; j < 8; j++) acc[i][j] += a[i] * bfr[j];
                }
                __syncthreads();
            }
            const float* bb = bias + (size_t)e * NB + nhh;
#pragma unroll
            for (int i = 0; i < 8; i++) {
                int slot = mBase + mh * 128 + ty * 8 + i;
                if (slot >= mEnd) continue;
#pragma unroll
                for (int j = 0; j < 8; j++) {
                    float v = acc[i][j] + bb[tx * 8 + j];
                    if (MODE == 0) {
                        g_H[(size_t)slot * D_FF + nhh + tx * 8 + j] = __float2half_rn(gelu_exact(v));
                    } else {
                        int tok = g_slot_token[slot];
                        atomicAdd(out + (size_t)tok * D_MODEL + nhh + tx * 8 + j,
                                  g_slot_w[slot] * v);
                    }
                }
            }
            __syncthreads();
        }
    }
#endif
}

// ---------------- host launch ----------------
extern "C" void kernel_launch(void* const* d_in, const int* in_sizes, int n_in,
                              void* d_out, int out_size)
{
    const float* x  = (const float*)d_in[0];
    const float* Wg = (const float*)d_in[1];
    const float* bg = (const float*)d_in[2];
    const float* W1 = (const float*)d_in[3];
    const float* b1 = (const float*)d_in[4];
    const float* W2 = (const float*)d_in[5];
    const float* b2 = (const float*)d_in[6];
    float* out = (float*)d_out;

    cudaFuncSetAttribute(moe_gemm<D_MODEL, 0>,
                         cudaFuncAttributeMaxDynamicSharedMemorySize, SMEM_TOTAL);
    cudaFuncSetAttribute(moe_gemm<D_FF, 1>,
                         cudaFuncAttributeMaxDynamicSharedMemorySize, SMEM_TOTAL);

    // zero the combine region (GEMM2 epilogue accumulates atomically)
    cudaMemsetAsync(out, 0, (size_t)T_TOKENS * D_MODEL * sizeof(float));

    transpose_kernel<<<dim3(D_FF / 32, D_MODEL / 64, N_EXPERTS), 256>>>(W1, D_MODEL, D_FF, 0);
    transpose_kernel<<<dim3(D_MODEL / 32, D_FF / 64, N_EXPERTS), 256>>>(W2, D_FF, D_MODEL, 1);

    init_kernel<<<1, 32>>>();
    gate_kernel<<<T_TOKENS / 64, 256>>>(x, Wg, bg, out + (size_t)T_TOKENS * D_MODEL);
    prefix_kernel<<<1, 32>>>();
    scatter_kernel<<<T_TOKENS / 256, 256>>>();
    gather_kernel<<<(TOTAL_SLOTS * 256) / 256, 256>>>(x);

    dim3 g1(TOTAL_SLOTS / BM, D_FF / BN, N_EXPERTS);      // 64 x 16 x 8 (early-exit x)
    moe_gemm<D_MODEL, 0><<<g1, 256, SMEM_TOTAL>>>(b1, out);

    dim3 g2(TOTAL_SLOTS / BM, D_MODEL / BN, N_EXPERTS);   // 64 x 4 x 8
    moe_gemm<D_FF, 1><<<g2, 256, SMEM_TOTAL>>>(b2, out);
}

// round 16
// speedup vs baseline: 1.9368x; 1.2021x over previous
#include <cuda_runtime.h>
#include <cuda_fp16.h>
#include <math.h>
#include <stdint.h>

#define D_MODEL   1024
#define N_EXPERTS 8
#define D_FF      4096
#define T_TOKENS  8192
#define TOTAL_SLOTS (T_TOKENS * 2)

#define BM 256            // two 128-row A tiles
#define BN 256            // two 128-col B tiles
#define BK 64             // fp16: 128B smem row = 64 halfs
#define NSTAGE 3
#define TILE16K 16384
#define STAGE_B (4 * TILE16K)        // A0 + A1 + B0 + B1 per stage
#define NTHREADS 288                 // 8 loader warps + 1 MMA warp

// smem layout (dynamic)
#define SM_TMEM  0
#define SM_FULL  16                       // full[NSTAGE]
#define SM_EMPTY (SM_FULL + NSTAGE * 8)   // empty[NSTAGE]
#define SM_DONE  (SM_EMPTY + NSTAGE * 8)
#define SM_TILES 2048
#define SMEM_TOTAL (SM_TILES + NSTAGE * STAGE_B)   // 198656 B

// fp16 idesc: M=128 (8<<24), N=128 (16<<17), f32 accum (1<<4), a/b = F16 (0)
#define IDESC_F16 ((8u << 24) | (16u << 17) | (1u << 4))

#if defined(__CUDA_ARCH__) && (defined(__CUDA_ARCH_FEAT_SM103_ALL) || defined(__CUDA_ARCH_FEAT_SM100_ALL) || defined(__CUDA_ARCH_FEAT_SM101_ALL))
#define USE_TCGEN05 1
#else
#define USE_TCGEN05 0
#endif

// ---------------- scratch (static __device__) ----------------
__device__ __half g_A1[(size_t)(TOTAL_SLOTS + BM) * D_MODEL];     // gathered fp16 x
__device__ __half g_H[(size_t)(TOTAL_SLOTS + BM) * D_FF];         // fp16 activations
__device__ float  g_Y[(size_t)TOTAL_SLOTS * D_MODEL];
__device__ __half g_W1t[(size_t)N_EXPERTS * D_FF * D_MODEL];      // [e][n][k] fp16
__device__ __half g_W2t[(size_t)N_EXPERTS * D_MODEL * D_FF];      // [e][n][k] fp16
__device__ int   g_slot_token[TOTAL_SLOTS];
__device__ int   g_tok2slot[T_TOKENS * 2];
__device__ float g_topk_w[T_TOKENS * 2];
__device__ int   g_topk_idx[T_TOKENS * 2];
__device__ int   g_cnt[N_EXPERTS];
__device__ int   g_off[N_EXPERTS + 1];
__device__ int   g_cursor[N_EXPERTS];

// ---------------- helpers ----------------
__device__ __forceinline__ float gelu_exact(float h) {
    return 0.5f * h * (1.0f + erff(h * 0.70710678118654752440f));
}
__device__ __forceinline__ uint32_t smem_u32(const void* p) {
    uint32_t a;
    asm("{ .reg .u64 t; cvta.to.shared.u64 t, %1; cvt.u32.u64 %0, t; }" : "=r"(a) : "l"(p));
    return a;
}

#if USE_TCGEN05
__device__ __forceinline__ uint32_t elect_one() {
    uint32_t pred;
    asm volatile("{\n\t.reg .pred p;\n\telect.sync _|p, 0xFFFFFFFF;\n\t"
                 "selp.b32 %0, 1, 0, p;\n\t}" : "=r"(pred));
    return pred;
}
static __device__ __forceinline__ uint64_t make_desc_sw128(uint32_t addr) {
    const uint64_t base = (uint64_t(2) << 61) | (uint64_t(1) << 46) |
                          (uint64_t(64) << 32) | (uint64_t(1) << 16);
    return base | ((uint64_t)(addr >> 4) & 0x3FFF);
}
__device__ __forceinline__ void mbar_wait(uint32_t mbar, uint32_t parity) {
    uint32_t done;
    asm volatile("{\n\t.reg .pred p;\n\t"
        "mbarrier.try_wait.parity.acquire.cta.shared::cta.b64 p, [%1], %2;\n\t"
        "selp.b32 %0, 1, 0, p;\n\t}"
        : "=r"(done) : "r"(mbar), "r"(parity) : "memory");
    while (!done) {
        asm volatile("{\n\t.reg .pred p;\n\t"
            "mbarrier.try_wait.parity.acquire.cta.shared::cta.b64 p, [%1], %2, 0x989680;\n\t"
            "selp.b32 %0, 1, 0, p;\n\t}"
            : "=r"(done) : "r"(mbar), "r"(parity) : "memory");
    }
}
#define CP_ASYNC16(dst, src) \
    asm volatile("cp.async.cg.shared.global [%0], [%1], 16;" :: "r"(dst), "l"(src))
// .noinc is load-bearing: the default variant pre-increments the pending count
// (net-zero phase effect). .noinc makes this a real counted arrival.
#define CP_MBAR_ARRIVE_NOINC(mbar) \
    asm volatile("cp.async.mbarrier.arrive.noinc.shared::cta.b64 [%0];" :: "r"(mbar) : "memory")

#define LDTM_X32(r, addr) \
    asm volatile( \
        "tcgen05.ld.sync.aligned.32x32b.x32.b32 " \
        "{%0, %1, %2, %3, %4, %5, %6, %7, " \
        " %8, %9, %10, %11, %12, %13, %14, %15, " \
        " %16, %17, %18, %19, %20, %21, %22, %23, " \
        " %24, %25, %26, %27, %28, %29, %30, %31}, [%32];" \
        : "=r"((r)[0]),  "=r"((r)[1]),  "=r"((r)[2]),  "=r"((r)[3]), \
          "=r"((r)[4]),  "=r"((r)[5]),  "=r"((r)[6]),  "=r"((r)[7]), \
          "=r"((r)[8]),  "=r"((r)[9]),  "=r"((r)[10]), "=r"((r)[11]), \
          "=r"((r)[12]), "=r"((r)[13]), "=r"((r)[14]), "=r"((r)[15]), \
          "=r"((r)[16]), "=r"((r)[17]), "=r"((r)[18]), "=r"((r)[19]), \
          "=r"((r)[20]), "=r"((r)[21]), "=r"((r)[22]), "=r"((r)[23]), \
          "=r"((r)[24]), "=r"((r)[25]), "=r"((r)[26]), "=r"((r)[27]), \
          "=r"((r)[28]), "=r"((r)[29]), "=r"((r)[30]), "=r"((r)[31]) \
        : "r"(addr))
#endif

// ---------------- routing kernels ----------------
__global__ void init_kernel() {
    int i = threadIdx.x;
    if (i < N_EXPERTS) g_cnt[i] = 0;
}

// gate: R11 version (proven 31us, 32 regs)
__global__ void gate_kernel(const float* __restrict__ x,
                            const float* __restrict__ Wg,
                            const float* __restrict__ bg,
                            float* __restrict__ gate_out)
{
    int warp = threadIdx.x >> 5;
    int lane = threadIdx.x & 31;
    int t = blockIdx.x * (blockDim.x >> 5) + warp;
    if (t >= T_TOKENS) return;

    float acc[N_EXPERTS];
#pragma unroll
    for (int e = 0; e < N_EXPERTS; e++) acc[e] = 0.0f;

    const float* xr = x + (size_t)t * D_MODEL;
    for (int d = lane; d < D_MODEL; d += 32) {
        float xv = xr[d];
        const float4 w0 = *(const float4*)(Wg + (size_t)d * N_EXPERTS);
        const float4 w1 = *(const float4*)(Wg + (size_t)d * N_EXPERTS + 4);
        acc[0] += xv * w0.x; acc[1] += xv * w0.y;
        acc[2] += xv * w0.z; acc[3] += xv * w0.w;
        acc[4] += xv * w1.x; acc[5] += xv * w1.y;
        acc[6] += xv * w1.z; acc[7] += xv * w1.w;
    }
#pragma unroll
    for (int e = 0; e < N_EXPERTS; e++) {
#pragma unroll
        for (int o = 16; o > 0; o >>= 1)
            acc[e] += __shfl_xor_sync(0xffffffffu, acc[e], o);
    }

    if (lane == 0) {
        float logit[N_EXPERTS];
        float mx = -1e30f;
#pragma unroll
        for (int e = 0; e < N_EXPERTS; e++) {
            logit[e] = acc[e] + bg[e];
            gate_out[(size_t)t * N_EXPERTS + e] = logit[e];
            mx = fmaxf(mx, logit[e]);
        }
        float p[N_EXPERTS];
        float sum = 0.0f;
#pragma unroll
        for (int e = 0; e < N_EXPERTS; e++) { p[e] = expf(logit[e] - mx); sum += p[e]; }
        float inv = 1.0f / sum;
#pragma unroll
        for (int e = 0; e < N_EXPERTS; e++) p[e] *= inv;

        int i0 = 0; float v0 = p[0];
#pragma unroll
        for (int e = 1; e < N_EXPERTS; e++) if (p[e] > v0) { v0 = p[e]; i0 = e; }
        int i1 = -1; float v1 = -1e30f;
#pragma unroll
        for (int e = 0; e < N_EXPERTS; e++) {
            if (e == i0) continue;
            if (p[e] > v1) { v1 = p[e]; i1 = e; }
        }
        g_topk_idx[t * 2 + 0] = i0; g_topk_w[t * 2 + 0] = v0;
        g_topk_idx[t * 2 + 1] = i1; g_topk_w[t * 2 + 1] = v1;
        atomicAdd(&g_cnt[i0], 1);
        atomicAdd(&g_cnt[i1], 1);
    }
}

__global__ void prefix_kernel() {
    if (threadIdx.x == 0) {
        int s = 0;
        for (int e = 0; e < N_EXPERTS; e++) {
            g_off[e] = s;
            g_cursor[e] = s;
            s += g_cnt[e];
        }
        g_off[N_EXPERTS] = s;
    }
}

__global__ void scatter_kernel() {
    int t = blockIdx.x * blockDim.x + threadIdx.x;
    if (t >= T_TOKENS) return;
#pragma unroll
    for (int k = 0; k < 2; k++) {
        int e = g_topk_idx[t * 2 + k];
        int pos = atomicAdd(&g_cursor[e], 1);
        g_slot_token[pos] = t;
        g_tok2slot[t * 2 + k] = pos;
    }
}

// gather + fp16-convert x rows into slot order
__global__ void gather_kernel(const float* __restrict__ x) {
    int idx = blockIdx.x * blockDim.x + threadIdx.x;
    int slot = idx >> 8;
    int c4 = idx & 255;
    int tok = g_slot_token[slot];
    float4 v = *(const float4*)(x + (size_t)tok * D_MODEL + c4 * 4);
    __half2 h0 = __floats2half2_rn(v.x, v.y);
    __half2 h1 = __floats2half2_rn(v.z, v.w);
    uint2 pk = make_uint2(*(uint32_t*)&h0, *(uint32_t*)&h1);
    *(uint2*)(g_A1 + (size_t)slot * D_MODEL + c4 * 4) = pk;
}

// transpose v2 + fp16 convert: in [z][R][C] fp32 -> out [z][C][R] fp16
__global__ __launch_bounds__(256) void transpose_kernel(const float* __restrict__ in,
                                                        int R, int C, int which)
{
    __shared__ float tile[64][33];
    __half* out = which ? g_W2t : g_W1t;
    size_t base = (size_t)blockIdx.z * (size_t)R * C;
    int c0 = blockIdx.x * 32, r0 = blockIdx.y * 64;
    int tid = threadIdx.x;
    {
        int r = tid >> 2;
        int cg = (tid & 3) * 8;
        const float* src = in + base + (size_t)(r0 + r) * C + c0 + cg;
        float4 v0 = *(const float4*)(src);
        float4 v1 = *(const float4*)(src + 4);
        tile[r][cg + 0] = v0.x; tile[r][cg + 1] = v0.y;
        tile[r][cg + 2] = v0.z; tile[r][cg + 3] = v0.w;
        tile[r][cg + 4] = v1.x; tile[r][cg + 5] = v1.y;
        tile[r][cg + 6] = v1.z; tile[r][cg + 7] = v1.w;
    }
    __syncthreads();
    {
        int c = tid >> 3;
        int rg = (tid & 7) * 8;
        __half2 h0 = __floats2half2_rn(tile[rg + 0][c], tile[rg + 1][c]);
        __half2 h1 = __floats2half2_rn(tile[rg + 2][c], tile[rg + 3][c]);
        __half2 h2 = __floats2half2_rn(tile[rg + 4][c], tile[rg + 5][c]);
        __half2 h3 = __floats2half2_rn(tile[rg + 6][c], tile[rg + 7][c]);
        uint4 pk;
        pk.x = *(uint32_t*)&h0; pk.y = *(uint32_t*)&h1;
        pk.z = *(uint32_t*)&h2; pk.w = *(uint32_t*)&h3;
        *(uint4*)(out + base + (size_t)(c0 + c) * R + (r0 + rg)) = pk;
    }
}

// ---------------- grouped GEMM (tcgen05 fp16, 256x256, warp-specialized) ----------------
// warps 0-7: loaders (cp.async + cp.async.mbarrier.arrive.noinc on full[s])
// warp 8:    MMA issuer (wait full -> fence -> 16 MMAs -> commit empty[s])
template<int KDIM, int MODE>
__global__ void __launch_bounds__(NTHREADS, 1) moe_gemm(const float* __restrict__ bias)
{
    extern __shared__ char smem[];
    const int tid = threadIdx.x;
    const int wid = tid >> 5, lane = tid & 31;

    const int e = blockIdx.z;
    const int mBase = g_off[e] + blockIdx.x * BM;
    const int mEnd  = g_off[e + 1];
    if (mBase >= mEnd) return;
    const int n0 = blockIdx.y * BN;

    const __half* Abase = (MODE == 0) ? g_A1 : g_H;
    const __half* Bt    = (MODE == 0) ? g_W1t : g_W2t;
    const int NB = (MODE == 0) ? D_FF : D_MODEL;
    const size_t eRowB = (size_t)e * NB;

#if USE_TCGEN05
    const uint32_t sb = smem_u32(smem);
    if (wid == 0) {
        asm volatile("tcgen05.alloc.cta_group::1.sync.aligned.shared::cta.b32 [%0], %1;"
                     :: "r"(sb + SM_TMEM), "r"(512u) : "memory");
        asm volatile("tcgen05.relinquish_alloc_permit.cta_group::1.sync.aligned;");
    }
    if (tid == 0) {
#pragma unroll
        for (int s = 0; s < NSTAGE; s++) {
            asm volatile("mbarrier.init.shared.b64 [%0], 256;"
                         :: "r"(sb + SM_FULL + s * 8) : "memory");   // 256 loader arrivals
            asm volatile("mbarrier.init.shared.b64 [%0], 1;"
                         :: "r"(sb + SM_EMPTY + s * 8) : "memory");  // 1 commit
        }
        asm volatile("mbarrier.init.shared.b64 [%0], 1;" :: "r"(sb + SM_DONE) : "memory");
    }
    __syncthreads();
    const uint32_t tmem = *(const uint32_t*)(smem + SM_TMEM);

    constexpr int NT = KDIM / BK;

    if (wid < 8) {
        // ---- loader path: 256 threads, 16x16B units each per stage ----
        uint32_t dstU[16];
        const char* srcU[16];
#pragma unroll
        for (int j = 0; j < 16; j++) {
            int u = tid + j * 256;           // 0..4095
            int tile = u >> 10;              // 0=A0,1=A1,2=B0,3=B1
            int v = u & 1023;
            int row = v >> 3, c16 = v & 7;
            uint32_t off = (uint32_t)(row * 128 + c16 * 16);
            uint32_t so = off ^ ((off >> 3) & 0x70);
            dstU[j] = (uint32_t)tile * TILE16K + so;
            const __half* src;
            if (tile < 2)
                src = Abase + (size_t)(mBase + tile * 128 + row) * KDIM;
            else
                src = Bt + (eRowB + n0 + (tile - 2) * 128 + row) * (size_t)KDIM;
            srcU[j] = (const char*)src + c16 * 16;
        }

        for (int pend = 0; pend < NT; pend++) {
            const int ps = pend % NSTAGE;
            if (pend >= NSTAGE) {
                // MMA that freed this stage ran at k-tile pend-NSTAGE:
                // (pend/NSTAGE - 1)-th commit on empty[ps]  (R11-proven formula)
                uint32_t pr = ((uint32_t)(pend / NSTAGE) - 1u) & 1u;
                mbar_wait(sb + SM_EMPTY + ps * 8, pr);
            }
            uint32_t sbase = sb + SM_TILES + ps * STAGE_B;
            size_t koff = (size_t)pend * 128;
#pragma unroll
            for (int j = 0; j < 16; j++) CP_ASYNC16(sbase + dstU[j], srcU[j] + koff);
            CP_MBAR_ARRIVE_NOINC(sb + SM_FULL + ps * 8);
        }
    } else {
        // ---- MMA warp ----
        if (elect_one()) {
            for (int k = 0; k < NT; k++) {
                const int s = k % NSTAGE;
                mbar_wait(sb + SM_FULL + s * 8, (uint32_t)(k / NSTAGE) & 1u);
                asm volatile("fence.proxy.async.shared::cta;" ::: "memory");
                uint32_t st = sb + SM_TILES + s * STAGE_B;
                uint64_t a0 = make_desc_sw128(st);
                uint64_t a1 = make_desc_sw128(st + TILE16K);
                uint64_t b0 = make_desc_sw128(st + 2 * TILE16K);
                uint64_t b1 = make_desc_sw128(st + 3 * TILE16K);
#pragma unroll
                for (int sub = 0; sub < 4; sub++) {
                    uint32_t en = (k > 0 || sub > 0) ? 1u : 0u;
#define MMA_F16(dtm, ad, bd) \
                    asm volatile( \
                        "{\n\t.reg .pred p;\n\tsetp.ne.u32 p, %4, 0;\n\t" \
                        "tcgen05.mma.cta_group::1.kind::f16 [%0], %1, %2, %3, " \
                        "{%5, %5, %5, %5}, p;\n\t}" \
                        :: "r"(dtm), "l"(ad), "l"(bd), "r"(IDESC_F16), "r"(en), "r"(0u) \
                        : "memory")
                    MMA_F16(tmem +   0, a0 + sub * 2, b0 + sub * 2);
                    MMA_F16(tmem + 128, a0 + sub * 2, b1 + sub * 2);
                    MMA_F16(tmem + 256, a1 + sub * 2, b0 + sub * 2);
                    MMA_F16(tmem + 384, a1 + sub * 2, b1 + sub * 2);
#undef MMA_F16
                }
                asm volatile(
                    "tcgen05.commit.cta_group::1.mbarrier::arrive::one.shared::cluster.b64 [%0];"
                    :: "r"(sb + SM_EMPTY + s * 8) : "memory");
            }
            asm volatile(
                "tcgen05.commit.cta_group::1.mbarrier::arrive::one.shared::cluster.b64 [%0];"
                :: "r"(sb + SM_DONE) : "memory");
        }
    }

    mbar_wait(sb + SM_DONE, 0);
    asm volatile("tcgen05.fence::after_thread_sync;" ::: "memory");

    // epilogue: loader warps 0-3 -> m-half 0 (acc @0,@128), 4-7 -> m-half 1 (@256,@384)
    if (wid < 8) {
        const int mh = wid >> 2;
        const int row = (wid & 3) * 32 + lane;
        const int slot = mBase + mh * 128 + row;
        const bool valid = slot < mEnd;
#pragma unroll
        for (int nh = 0; nh < 2; nh++) {
            const float* bb = bias + (size_t)e * NB + n0 + nh * 128;
            const uint32_t tm = tmem + mh * 256 + nh * 128;
            __half* dstH = 0; float* dstY = 0;
            if (valid) {
                if (MODE == 0) dstH = g_H + (size_t)slot * D_FF + n0 + nh * 128;
                else           dstY = g_Y + (size_t)slot * D_MODEL + n0 + nh * 128;
            }
#pragma unroll
            for (int nb = 0; nb < 4; nb++) {
                uint32_t dr[32];
                LDTM_X32(dr, tm + nb * 32);
                asm volatile("tcgen05.wait::ld.sync.aligned;" ::: "memory");
                if (valid) {
#pragma unroll
                    for (int q = 0; q < 8; q++) {
                        float v0 = __uint_as_float(dr[q * 4 + 0]) + bb[nb * 32 + q * 4 + 0];
                        float v1 = __uint_as_float(dr[q * 4 + 1]) + bb[nb * 32 + q * 4 + 1];
                        float v2 = __uint_as_float(dr[q * 4 + 2]) + bb[nb * 32 + q * 4 + 2];
                        float v3 = __uint_as_float(dr[q * 4 + 3]) + bb[nb * 32 + q * 4 + 3];
                        if (MODE == 0) {
                            __half2 h0 = __floats2half2_rn(gelu_exact(v0), gelu_exact(v1));
                            __half2 h1 = __floats2half2_rn(gelu_exact(v2), gelu_exact(v3));
                            uint2 pk = make_uint2(*(uint32_t*)&h0, *(uint32_t*)&h1);
                            *(uint2*)(dstH + nb * 32 + q * 4) = pk;
                        } else {
                            float4 o; o.x = v0; o.y = v1; o.z = v2; o.w = v3;
                            *(float4*)(dstY + nb * 32 + q * 4) = o;
                        }
                    }
                }
            }
        }
    }
    __syncthreads();
    if (wid == 0) {
        asm volatile("tcgen05.dealloc.cta_group::1.sync.aligned.b32 %0, %1;"
                     :: "r"(tmem), "r"(512u));
    }
#else
    // ---------- SIMT fallback (non-'a' pass only; runtime uses the 'a' cubin) ----------
    __syncthreads();
    float (*As)[132] = (float(*)[132])(smem + SM_TILES);
    float (*Bs)[132] = (float(*)[132])(smem + SM_TILES + 16 * 132 * 4);
    const int ty = tid >> 4, tx = tid & 15;
    const int lr = tid >> 1;
    const int lc = (tid & 1) * 8;
    const bool active = tid < 256;

    for (int mh = 0; mh < 2; mh++) {
        const __half* arow = Abase + (size_t)(mBase + mh * 128 + (active ? lr : 0)) * KDIM;
        for (int nh = 0; nh < 2; nh++) {
            const int nhh = n0 + nh * 128;
            const __half* brow = Bt + (eRowB + nhh + (active ? lr : 0)) * (size_t)KDIM + lc;
            float acc[8][8];
#pragma unroll
            for (int i = 0; i < 8; i++)
#pragma unroll
                for (int j = 0; j < 8; j++) acc[i][j] = 0.0f;

            for (int k0 = 0; k0 < KDIM; k0 += 16) {
                if (active) {
#pragma unroll
                    for (int q = 0; q < 8; q++) {
                        As[lc + q][lr] = __half2float(arow[k0 + lc + q]);
                        Bs[lc + q][lr] = __half2float(brow[k0 + q]);
                    }
                }
                __syncthreads();
                if (active) {
#pragma unroll
                    for (int kk = 0; kk < 16; kk++) {
                        float a[8], bfr[8];
#pragma unroll
                        for (int i = 0; i < 8; i++) a[i] = As[kk][ty * 8 + i];
#pragma unroll
                        for (int j = 0; j < 8; j++) bfr[j] = Bs[kk][tx * 8 + j];
#pragma unroll
                        for (int i = 0; i < 8; i++)
#pragma unroll
                            for (int j = 0; j < 8; j++) acc[i][j] += a[i] * bfr[j];
                    }
                }
                __syncthreads();
            }
            if (active) {
                const float* bb = bias + (size_t)e * NB + nhh;
#pragma unroll
                for (int i = 0; i < 8; i++) {
                    int slot = mBase + mh * 128 + ty * 8 + i;
                    if (slot >= mEnd) continue;
#pragma unroll
                    for (int j = 0; j < 8; j++) {
                        float v = acc[i][j] + bb[tx * 8 + j];
                        if (MODE == 0)
                            g_H[(size_t)slot * D_FF + nhh + tx * 8 + j] = __float2half_rn(gelu_exact(v));
                        else
                            g_Y[(size_t)slot * D_MODEL + nhh + tx * 8 + j] = v;
                    }
                }
            }
            __syncthreads();
        }
    }
#endif
}

// ---------------- combine ----------------
__global__ void combine_kernel(float* __restrict__ out) {
    int idx = blockIdx.x * blockDim.x + threadIdx.x;
    int t  = idx >> 8;
    int d4 = idx & 255;
    int s0 = g_tok2slot[t * 2 + 0], s1 = g_tok2slot[t * 2 + 1];
    float w0 = g_topk_w[t * 2 + 0], w1 = g_topk_w[t * 2 + 1];
    float4 a = *(const float4*)(g_Y + (size_t)s0 * D_MODEL + d4 * 4);
    float4 b = *(const float4*)(g_Y + (size_t)s1 * D_MODEL + d4 * 4);
    float4 o;
    o.x = w0 * a.x + w1 * b.x;
    o.y = w0 * a.y + w1 * b.y;
    o.z = w0 * a.z + w1 * b.z;
    o.w = w0 * a.w + w1 * b.w;
    *(float4*)(out + (size_t)t * D_MODEL + d4 * 4) = o;
}

// ---------------- host launch ----------------
extern "C" void kernel_launch(void* const* d_in, const int* in_sizes, int n_in,
                              void* d_out, int out_size)
{
    const float* x  = (const float*)d_in[0];
    const float* Wg = (const float*)d_in[1];
    const float* bg = (const float*)d_in[2];
    const float* W1 = (const float*)d_in[3];
    const float* b1 = (const float*)d_in[4];
    const float* W2 = (const float*)d_in[5];
    const float* b2 = (const float*)d_in[6];
    float* out = (float*)d_out;

    cudaFuncSetAttribute(moe_gemm<D_MODEL, 0>,
                         cudaFuncAttributeMaxDynamicSharedMemorySize, SMEM_TOTAL);
    cudaFuncSetAttribute(moe_gemm<D_FF, 1>,
                         cudaFuncAttributeMaxDynamicSharedMemorySize, SMEM_TOTAL);

    transpose_kernel<<<dim3(D_FF / 32, D_MODEL / 64, N_EXPERTS), 256>>>(W1, D_MODEL, D_FF, 0);
    transpose_kernel<<<dim3(D_MODEL / 32, D_FF / 64, N_EXPERTS), 256>>>(W2, D_FF, D_MODEL, 1);

    init_kernel<<<1, 32>>>();
    gate_kernel<<<T_TOKENS / 8, 256>>>(x, Wg, bg, out + (size_t)T_TOKENS * D_MODEL);
    prefix_kernel<<<1, 32>>>();
    scatter_kernel<<<T_TOKENS / 256, 256>>>();
    gather_kernel<<<(TOTAL_SLOTS * 256) / 256, 256>>>(x);

    dim3 g1(TOTAL_SLOTS / BM, D_FF / BN, N_EXPERTS);      // 64 x 16 x 8 (early-exit x)
    moe_gemm<D_MODEL, 0><<<g1, NTHREADS, SMEM_TOTAL>>>(b1);

    dim3 g2(TOTAL_SLOTS / BM, D_MODEL / BN, N_EXPERTS);   // 64 x 4 x 8
    moe_gemm<D_FF, 1><<<g2, NTHREADS, SMEM_TOTAL>>>(b2);

    combine_kernel<<<(T_TOKENS * 256) / 256, 256>>>(out);
}